// round 15
// baseline (speedup 1.0000x reference)
#include <cuda_runtime.h>
#include <cuda.h>
#include <cuda_fp16.h>
#include <math.h>
#include <stdint.h>

// Problem constants (fixed shapes)
#define B_   16
#define C_   384
#define C3   1152
#define HW   4096
#define NH   8
#define DH   48
#define NCH  16
#define CHUNK 256
#define EPSN 1e-12f
#define KTOT 384
#define NTB  16          // n-tiles per batch (HW/256)

// GEMM smem geometry: block 128(M) x 256(N) x 32(K), 4-stage cp.async
#define LDA 40
#define LDB 264
#define A_SZ   (128 * LDA * 2)            // 10240
#define B_SZ   (32 * LDB * 2)             // 16896
#define B_OFF  A_SZ
#define SST    (B_OFF + B_SZ)             // 27136
#define NSTG   4
#define GSMEM  (NSTG * SST)               // 108544
#define PGRID  148

// ---------------- scratch (__device__ globals; no runtime alloc) -----------
__device__ __align__(128) __half g_qkv16[(size_t)B_ * C3 * HW];     // 151 MB
__device__ float g_inv[B_ * 2 * C_];
__device__ float g_Spart[NCH][B_ * NH][DH * DH];
__device__ __align__(128) __half g_W0[C3 * C_];                     // Wh [m][k]
__device__ __align__(128) __half g_T0[(size_t)B_ * C_ * HW];        // X fp16 [k][n]
__device__ __align__(128) __half g_We0[B_ * C_ * C_];               // Weh [m][k]

// ---------------- PTX helpers ----------------------------------------------
__device__ __forceinline__ uint32_t smem_u32(const void* p) {
    uint32_t a;
    asm("{ .reg .u64 t; cvta.to.shared.u64 t, %1; cvt.u32.u64 %0, t; }"
        : "=r"(a) : "l"(p));
    return a;
}
__device__ __forceinline__ void ldm_x4(uint32_t* r, uint32_t addr) {
    asm volatile("ldmatrix.sync.aligned.m8n8.x4.shared.b16 {%0,%1,%2,%3}, [%4];"
        : "=r"(r[0]), "=r"(r[1]), "=r"(r[2]), "=r"(r[3]) : "r"(addr));
}
__device__ __forceinline__ void ldm_x4_t(uint32_t* r, uint32_t addr) {
    asm volatile("ldmatrix.sync.aligned.m8n8.x4.trans.shared.b16 {%0,%1,%2,%3}, [%4];"
        : "=r"(r[0]), "=r"(r[1]), "=r"(r[2]), "=r"(r[3]) : "r"(addr));
}
__device__ __forceinline__ void mma_h(float* c, const uint32_t* a,
                                      uint32_t b0, uint32_t b1) {
    asm volatile(
        "mma.sync.aligned.m16n8k16.row.col.f32.f16.f16.f32 "
        "{%0,%1,%2,%3}, {%4,%5,%6,%7}, {%8,%9}, {%0,%1,%2,%3};"
        : "+f"(c[0]), "+f"(c[1]), "+f"(c[2]), "+f"(c[3])
        : "r"(a[0]), "r"(a[1]), "r"(a[2]), "r"(a[3]), "r"(b0), "r"(b1));
}
__device__ __forceinline__ void cpa16(uint32_t s, const void* g) {
    asm volatile("cp.async.cg.shared.global [%0], [%1], 16;" :: "r"(s), "l"(g));
}
__device__ __forceinline__ void cpa_commit() {
    asm volatile("cp.async.commit_group;");
}
template <int N> __device__ __forceinline__ void cpa_wait() {
    asm volatile("cp.async.wait_group %0;" :: "n"(N));
}

// ---------------------------------------------------------------------------
// PERSISTENT fp16 GEMM: C[b][M,4096] = A[M,384] @ B[384,4096].
// A [m][k]; B [k][n]. Block tile 128x256x32, 8 warps, warp 64x64.
// Grid = 148 persistent CTAs; each owns tiles bid, bid+148, ... with the
// 4-stage cp.async ring running continuously across tile boundaries
// (one barrier per k-step; acc reset at kt==0; register epilogue at kt==11).
// Tile linearization: m fastest (consecutive tiles share the B n-tile).
// outH=1 -> fp16 output; outH=0 -> fp32 output.
// ---------------------------------------------------------------------------
__global__ __launch_bounds__(256, 1)
void gemm_h1(const __half* __restrict__ Ahg, size_t aBatch,
             const __half* __restrict__ Bg, size_t bBatch,
             void* __restrict__ Cvoid, size_t cBatch, int outH, int MT)
{
    extern __shared__ char smem[];
    const uint32_t sbase = smem_u32(smem);

    const int t    = threadIdx.x;
    const int lane = t & 31;
    const int wid  = t >> 5;
    const int warpM = (wid >> 2) * 64;
    const int warpN = (wid & 3) * 64;

    const int total   = MT * NTB * B_;
    const int myfirst = blockIdx.x;
    int ntiles = 0;
    for (int tl = myfirst; tl < total; tl += PGRID) ntiles++;
    if (ntiles == 0) return;
    const int tsteps = ntiles * 12;

    const int g  = lane >> 3;
    const int lr = lane & 7;
    const uint32_t aLane = (uint32_t)(((g & 1) * 8 + lr) * LDA + (g >> 1) * 8) * 2;
    const uint32_t bLane = (uint32_t)(((g & 1) * 8 + lr) * LDB + (g >> 1) * 8) * 2;

    auto load_step = [&](int ls) {
        const int tl = myfirst + (ls / 12) * PGRID;
        const int kt = ls % 12;
        const int mi = tl % MT;
        const int nb = tl / MT;
        const int ni = nb & (NTB - 1);
        const int bb = nb >> 4;
        const __half* Asrc = Ahg + (size_t)bb * aBatch + (size_t)(mi * 128) * KTOT;
        const __half* Bsrc = Bg + (size_t)bb * bBatch;
        const int n0 = ni * 256;
        const uint32_t sb = sbase + (ls % NSTG) * SST;
#pragma unroll
        for (int it = 0; it < 2; it++) {          // A: 512 x 16B
            int c = t + it * 256;
            int r = c >> 2, kc = c & 3;
            cpa16(sb + r * (LDA * 2) + kc * 16,
                  Asrc + (size_t)r * KTOT + kt * 32 + kc * 8);
        }
#pragma unroll
        for (int it = 0; it < 4; it++) {          // B: 1024 x 16B
            int c = t + it * 256;
            int r = c >> 5, nc = c & 31;
            cpa16(sb + B_OFF + r * (LDB * 2) + nc * 16,
                  Bsrc + (size_t)(kt * 32 + r) * HW + n0 + nc * 8);
        }
        cpa_commit();
    };

    load_step(0);
    if (1 < tsteps) load_step(1);
    if (2 < tsteps) load_step(2);

    float acc[4][8][4];

    for (int ls = 0; ls < tsteps; ls++) {
        const int rem = tsteps - 1 - ls;
        if (rem >= 2)      cpa_wait<2>();
        else if (rem == 1) cpa_wait<1>();
        else               cpa_wait<0>();
        __syncthreads();
        if (ls + 3 < tsteps) load_step(ls + 3);

        const int kt = ls % 12;
        if (kt == 0) {
#pragma unroll
            for (int i = 0; i < 4; i++)
#pragma unroll
                for (int j = 0; j < 8; j++)
#pragma unroll
                    for (int e = 0; e < 4; e++) acc[i][j][e] = 0.f;
        }

        const uint32_t sb = sbase + (ls % NSTG) * SST;
#pragma unroll
        for (int k16 = 0; k16 < 2; k16++) {
            uint32_t Ah[4][4];
#pragma unroll
            for (int i = 0; i < 4; i++)
                ldm_x4(Ah[i], sb + aLane
                              + (uint32_t)((warpM + i * 16) * LDA + k16 * 16) * 2);
            uint32_t Bf[8][2];
#pragma unroll
            for (int p = 0; p < 4; p++) {
                uint32_t r[4];
                uint32_t bo = sb + B_OFF + bLane
                            + (uint32_t)(k16 * 16 * LDB + warpN + p * 16) * 2;
                ldm_x4_t(r, bo);
                Bf[p * 2][0] = r[0]; Bf[p * 2][1] = r[1];
                Bf[p * 2 + 1][0] = r[2]; Bf[p * 2 + 1][1] = r[3];
            }
#pragma unroll
            for (int i = 0; i < 4; i++)
#pragma unroll
                for (int j = 0; j < 8; j++)
                    mma_h(acc[i][j], Ah[i], Bf[j][0], Bf[j][1]);
        }

        if (kt == 11) {
            // epilogue for the finished tile (registers only; in-flight
            // cp.asyncs target other ring stages)
            const int tl = myfirst + (ls / 12) * PGRID;
            const int mi = tl % MT;
            const int nb = tl / MT;
            const int ni = nb & (NTB - 1);
            const int bb = nb >> 4;
            const int m0 = mi * 128, n0 = ni * 256;
            const int erow = lane >> 2;
            const int ecol = (lane & 3) * 2;
            if (outH) {
                __half* Cp = (__half*)Cvoid + (size_t)bb * cBatch;
#pragma unroll
                for (int i = 0; i < 4; i++)
#pragma unroll
                    for (int j = 0; j < 8; j++) {
                        __half* base = Cp + (size_t)(m0 + warpM + i * 16 + erow) * HW
                                          + n0 + warpN + j * 8 + ecol;
                        __half2 v01 = __floats2half2_rn(acc[i][j][0], acc[i][j][1]);
                        __half2 v23 = __floats2half2_rn(acc[i][j][2], acc[i][j][3]);
                        *(__half2*)base = v01;
                        *(__half2*)(base + 8 * HW) = v23;
                    }
            } else {
                float* Cp = (float*)Cvoid + (size_t)bb * cBatch;
#pragma unroll
                for (int i = 0; i < 4; i++)
#pragma unroll
                    for (int j = 0; j < 8; j++) {
                        float* base = Cp + (size_t)(m0 + warpM + i * 16 + erow) * HW
                                         + n0 + warpN + j * 8 + ecol;
                        *(float2*)base = make_float2(acc[i][j][0], acc[i][j][1]);
                        *(float2*)(base + 8 * HW) = make_float2(acc[i][j][2], acc[i][j][3]);
                    }
            }
        }
    }
}

// ---------------------------------------------------------------------------
// Combined fp32 -> fp16 convert for X (first nx4 float4's) and W (next nw4).
// ---------------------------------------------------------------------------
__global__ __launch_bounds__(256)
void convprep(const float* __restrict__ x, __half* __restrict__ xh, int nx4,
              const float* __restrict__ w, __half* __restrict__ wh, int nw4)
{
    int i = blockIdx.x * 256 + threadIdx.x;
    const float* src;
    __half* dst;
    int j;
    if (i < nx4)            { src = x; dst = xh; j = i; }
    else if (i < nx4 + nw4) { src = w; dst = wh; j = i - nx4; }
    else return;
    float4 v = ((const float4*)src)[j];
    __half2 a = __floats2half2_rn(v.x, v.y);
    __half2 b = __floats2half2_rn(v.z, v.w);
    ((uint2*)dst)[j] = make_uint2(*(uint32_t*)&a, *(uint32_t*)&b);
}

// ---------------------------------------------------------------------------
// Depthwise 3x3 SAME conv on fp16 qkv, in place (from R14, passing).
// ---------------------------------------------------------------------------
__global__ __launch_bounds__(256)
void dwconv3x3(__half* __restrict__ qkv, const float* __restrict__ wdw,
               float* __restrict__ inv)
{
    const int plane = blockIdx.x;
    const int b     = plane / C3;
    const int ch    = plane % C3;
    __half* p = qkv + (size_t)plane * HW;

    __shared__ __align__(16) __half s[66][88];
    const int t = threadIdx.x;

    {
        const int hr = (t >> 2) + 1;
        const int hc = (t & 1) ? 7 : 6;
        s[hr][hc + ((t & 2) ? 66 : 0)] = __ushort_as_half(0);
        if (t < 88) { s[0][t] = __ushort_as_half(0); s[65][t] = __ushort_as_half(0); }
    }
#pragma unroll
    for (int it = 0; it < 2; it++) {
        int i = t + it * 256;
        int y = i >> 3, x8 = (i & 7) * 8;
        *(uint4*)&s[y + 1][x8 + 8] = *(const uint4*)&p[y * 64 + x8];
    }

    float w[9];
#pragma unroll
    for (int j = 0; j < 9; j++) w[j] = wdw[ch * 9 + j];
    __syncthreads();

    const int y  = (t >> 3) * 2;
    const int x8 = (t & 7) * 8;

    float v[4][12];
#pragma unroll
    for (int r = 0; r < 4; r++) {
        __half2 hh[12];
        *(uint4*)&hh[0] = *(uint4*)&s[y + r][x8];
        *(uint4*)&hh[4] = *(uint4*)&s[y + r][x8 + 8];
        *(uint4*)&hh[8] = *(uint4*)&s[y + r][x8 + 16];
#pragma unroll
        for (int u = 0; u < 6; u++) {
            float2 f = __half22float2(hh[3 + u]);
            v[r][2 * u]     = f.x;
            v[r][2 * u + 1] = f.y;
        }
    }

    float o[2][8];
#pragma unroll
    for (int rr = 0; rr < 2; rr++)
#pragma unroll
        for (int j = 0; j < 8; j++) {
            float a = 0.f;
#pragma unroll
            for (int dy = 0; dy < 3; dy++)
#pragma unroll
                for (int dx = 0; dx < 3; dx++)
                    a = fmaf(v[rr + dy][j + 1 + dx], w[dy * 3 + dx], a);
            o[rr][j] = a;
        }

    float ss = 0.f;
#pragma unroll
    for (int rr = 0; rr < 2; rr++) {
        __half2 h0 = __floats2half2_rn(o[rr][0], o[rr][1]);
        __half2 h1 = __floats2half2_rn(o[rr][2], o[rr][3]);
        __half2 h2 = __floats2half2_rn(o[rr][4], o[rr][5]);
        __half2 h3 = __floats2half2_rn(o[rr][6], o[rr][7]);
        *(uint4*)&p[(y + rr) * 64 + x8] = make_uint4(
            *(uint32_t*)&h0, *(uint32_t*)&h1, *(uint32_t*)&h2, *(uint32_t*)&h3);
#pragma unroll
        for (int j = 0; j < 8; j++) ss = fmaf(o[rr][j], o[rr][j], ss);
    }

    if (ch < 2 * C_) {
        for (int off = 16; off > 0; off >>= 1)
            ss += __shfl_down_sync(0xffffffffu, ss, off);
        __shared__ float red[8];
        if ((t & 31) == 0) red[t >> 5] = ss;
        __syncthreads();
        if (t == 0) {
            float tot = 0.f;
#pragma unroll
            for (int i = 0; i < 8; i++) tot += red[i];
            inv[b * 2 * C_ + ch] = 1.f / fmaxf(sqrtf(tot), EPSN);
        }
    }
}

// ---------------------------------------------------------------------------
// Attention scores via mma.sync (partial unnormalized Gram), 16 k-chunks.
// ---------------------------------------------------------------------------
#define LDQ 72
__global__ __launch_bounds__(96)
void attn_scores(const __half* __restrict__ qkv)
{
    const int bh    = blockIdx.y;
    const int b     = bh >> 3;
    const int h     = bh & 7;
    const int chunk = blockIdx.x;
    const int t    = threadIdx.x;
    const int lane = t & 31;
    const int wid  = t >> 5;

    const __half* qbase = qkv + ((size_t)b * C3 + h * DH) * HW;
    const __half* kbase = qbase + (size_t)C_ * HW;

    __shared__ __align__(16) __half Qs[DH][LDQ];
    __shared__ __align__(16) __half Ks[DH][LDQ];
    const uint32_t qb = smem_u32(&Qs[0][0]);
    const uint32_t kb2 = smem_u32(&Ks[0][0]);

    const int g  = lane >> 3;
    const int lr = lane & 7;
    const uint32_t aLane = (uint32_t)(((g & 1) * 8 + lr) * LDQ + (g >> 1) * 8) * 2;
    const uint32_t bLane = (uint32_t)((wid * 16 + (g >> 1) * 8 + lr) * LDQ + (g & 1) * 8) * 2;

    float acc[3][2][4];
#pragma unroll
    for (int i = 0; i < 3; i++)
#pragma unroll
        for (int p = 0; p < 2; p++)
#pragma unroll
            for (int e = 0; e < 4; e++) acc[i][p][e] = 0.f;

    const int kb0 = chunk * CHUNK;
    for (int kt = 0; kt < CHUNK / 64; kt++) {
        for (int i = t; i < DH * 8; i += 96) {
            int r  = i >> 3;
            int c8 = (i & 7) * 8;
            *(uint4*)&Qs[r][c8] = *(const uint4*)&qbase[(size_t)r * HW + kb0 + kt * 64 + c8];
            *(uint4*)&Ks[r][c8] = *(const uint4*)&kbase[(size_t)r * HW + kb0 + kt * 64 + c8];
        }
        __syncthreads();

#pragma unroll
        for (int k16 = 0; k16 < 4; k16++) {
            uint32_t Aq[3][4];
#pragma unroll
            for (int i = 0; i < 3; i++)
                ldm_x4(Aq[i], qb + aLane + (uint32_t)(i * 16 * LDQ + k16 * 16) * 2);
            uint32_t r[4];
            ldm_x4(r, kb2 + bLane + (uint32_t)(k16 * 16) * 2);
#pragma unroll
            for (int i = 0; i < 3; i++) {
                mma_h(acc[i][0], Aq[i], r[0], r[1]);
                mma_h(acc[i][1], Aq[i], r[2], r[3]);
            }
        }
        __syncthreads();
    }

    const int erow = lane >> 2;
    const int ecol = (lane & 3) * 2;
    float* sp = &g_Spart[chunk][bh][0];
#pragma unroll
    for (int i = 0; i < 3; i++)
#pragma unroll
        for (int p = 0; p < 2; p++) {
            float* base = sp + (i * 16 + erow) * DH + wid * 16 + p * 8 + ecol;
            *(float2*)base = make_float2(acc[i][p][0], acc[i][p][1]);
            *(float2*)(base + 8 * DH) = make_float2(acc[i][p][2], acc[i][p][3]);
        }
}

// ---------------------------------------------------------------------------
// FUSED: reduce partials + norm scaling + temperature + softmax + W_eff.
// ---------------------------------------------------------------------------
__global__ __launch_bounds__(256)
void soft_weff(const float* __restrict__ temp, const float* __restrict__ inv,
               const float* __restrict__ wp, __half* __restrict__ eh)
{
    const int bh = blockIdx.x;
    const int b  = bh >> 3;
    const int h  = bh & 7;
    const int t  = threadIdx.x;

    __shared__ float As[DH][DH + 1];
    for (int i = t; i < DH * DH; i += 256) {
        float s = 0.f;
#pragma unroll
        for (int ch = 0; ch < NCH; ch++)
            s += g_Spart[ch][bh][i];
        As[i / DH][i % DH] = s;
    }
    __syncthreads();

    if (t < DH) {
        const float* ivq = inv + b * 2 * C_ + h * DH;
        const float* ivk = ivq + C_;
        const float rowscale = ivq[t] * temp[h];
        float vals[DH];
        float m = -INFINITY;
#pragma unroll
        for (int c = 0; c < DH; c++) {
            vals[c] = As[t][c] * rowscale * ivk[c];
            m = fmaxf(m, vals[c]);
        }
        float sum = 0.f;
#pragma unroll
        for (int c = 0; c < DH; c++) {
            vals[c] = expf(vals[c] - m);
            sum += vals[c];
        }
        float is = 1.f / sum;
#pragma unroll
        for (int c = 0; c < DH; c++) As[t][c] = vals[c] * is;
    }
    __syncthreads();

    for (int o = t; o < C_; o += 256) {
        float wrow[DH];
#pragma unroll
        for (int d = 0; d < DH; d++) wrow[d] = wp[(size_t)o * C_ + h * DH + d];
#pragma unroll 4
        for (int e = 0; e < DH; e++) {
            float acc = 0.f;
#pragma unroll
            for (int d = 0; d < DH; d++) acc = fmaf(wrow[d], As[d][e], acc);
            eh[((size_t)b * C_ + o) * C_ + h * DH + e] = __float2half(acc);
        }
    }
}

// ---------------------------------------------------------------------------
extern "C" void kernel_launch(void* const* d_in, const int* in_sizes, int n_in,
                              void* d_out, int out_size)
{
    const float* x      = (const float*)d_in[0];
    const float* w_qkv  = (const float*)d_in[1];
    const float* w_dw   = (const float*)d_in[2];
    const float* w_proj = (const float*)d_in[3];
    const float* temp   = (const float*)d_in[4];
    float* out = (float*)d_out;

    float* inv;
    __half *qkv16, *W0, *T0, *We0;
    cudaGetSymbolAddress((void**)&qkv16, g_qkv16);
    cudaGetSymbolAddress((void**)&inv, g_inv);
    cudaGetSymbolAddress((void**)&W0, g_W0);
    cudaGetSymbolAddress((void**)&T0, g_T0);
    cudaGetSymbolAddress((void**)&We0, g_We0);

    cudaFuncSetAttribute(gemm_h1, cudaFuncAttributeMaxDynamicSharedMemorySize, GSMEM);

    const int nx4 = B_ * C_ * HW / 4;
    const int nw4 = C3 * C_ / 4;
    // 1) X,W -> fp16 (one launch)
    convprep<<<(nx4 + nw4 + 255) / 256, 256>>>(x, T0, nx4, w_qkv, W0, nw4);
    // 2) qkv16 = W_qkv @ X  (persistent, fp16 output)
    gemm_h1<<<PGRID, 256, GSMEM>>>(
        W0, 0, T0, (size_t)C_ * HW, qkv16, (size_t)C3 * HW, 1, C3 / 128);
    // 3) dwconv in place on fp16 qkv + fused q/k norms
    dwconv3x3<<<B_ * C3, 256>>>(qkv16, w_dw, inv);
    // 4) attention scores via mma (16 chunks)
    attn_scores<<<dim3(NCH, B_ * NH), 96>>>(qkv16);
    // 5) fused softmax + W_eff
    soft_weff<<<B_ * NH, 256>>>(temp, inv, w_proj, We0);
    // 6) out = W_eff[b] @ V  (persistent, fp32 output)
    gemm_h1<<<PGRID, 256, GSMEM>>>(
        We0, (size_t)C_ * C_, qkv16 + (size_t)2 * C_ * HW, (size_t)C3 * HW,
        out, (size_t)C_ * HW, 0, C_ / 128);
}

// round 16
// speedup vs baseline: 1.0627x; 1.0627x over previous
#include <cuda_runtime.h>
#include <cuda.h>
#include <cuda_fp16.h>
#include <math.h>
#include <stdint.h>

// Problem constants (fixed shapes)
#define B_   16
#define C_   384
#define C3   1152
#define HW   4096
#define NH   8
#define DH   48
#define NCH  8
#define CHUNK 512
#define EPSN 1e-12f
#define KTOT 384

// GEMM smem geometry: block 128(M) x 256(N) x 32(K), 4-stage cp.async
#define LDA 40
#define LDB 264
#define A_SZ   (128 * LDA * 2)            // 10240
#define B_SZ   (32 * LDB * 2)             // 16896
#define B_OFF  A_SZ
#define SST    (B_OFF + B_SZ)             // 27136
#define NSTG   4
#define GSMEM  (NSTG * SST)               // 108544

// ---------------- scratch (__device__ globals; no runtime alloc) -----------
__device__ __align__(128) __half g_qkv16[(size_t)B_ * C3 * HW];     // 151 MB
__device__ float g_inv[B_ * 2 * C_];
__device__ float g_Spart[NCH][B_ * NH][DH * DH];
__device__ __align__(128) __half g_W0[C3 * C_];                     // Wh [m][k]
__device__ __align__(128) __half g_T0[(size_t)B_ * C_ * HW];        // X fp16 [k][n]
__device__ __align__(128) __half g_We0[B_ * C_ * C_];               // Weh [m][k]

// ---------------- PTX helpers ----------------------------------------------
__device__ __forceinline__ uint32_t smem_u32(const void* p) {
    uint32_t a;
    asm("{ .reg .u64 t; cvta.to.shared.u64 t, %1; cvt.u32.u64 %0, t; }"
        : "=r"(a) : "l"(p));
    return a;
}
__device__ __forceinline__ void ldm_x4(uint32_t* r, uint32_t addr) {
    asm volatile("ldmatrix.sync.aligned.m8n8.x4.shared.b16 {%0,%1,%2,%3}, [%4];"
        : "=r"(r[0]), "=r"(r[1]), "=r"(r[2]), "=r"(r[3]) : "r"(addr));
}
__device__ __forceinline__ void ldm_x4_t(uint32_t* r, uint32_t addr) {
    asm volatile("ldmatrix.sync.aligned.m8n8.x4.trans.shared.b16 {%0,%1,%2,%3}, [%4];"
        : "=r"(r[0]), "=r"(r[1]), "=r"(r[2]), "=r"(r[3]) : "r"(addr));
}
__device__ __forceinline__ void mma_h(float* c, const uint32_t* a,
                                      uint32_t b0, uint32_t b1) {
    asm volatile(
        "mma.sync.aligned.m16n8k16.row.col.f32.f16.f16.f32 "
        "{%0,%1,%2,%3}, {%4,%5,%6,%7}, {%8,%9}, {%0,%1,%2,%3};"
        : "+f"(c[0]), "+f"(c[1]), "+f"(c[2]), "+f"(c[3])
        : "r"(a[0]), "r"(a[1]), "r"(a[2]), "r"(a[3]), "r"(b0), "r"(b1));
}
__device__ __forceinline__ void cpa16(uint32_t s, const void* g) {
    asm volatile("cp.async.cg.shared.global [%0], [%1], 16;" :: "r"(s), "l"(g));
}
__device__ __forceinline__ void cpa_commit() {
    asm volatile("cp.async.commit_group;");
}
template <int N> __device__ __forceinline__ void cpa_wait() {
    asm volatile("cp.async.wait_group %0;" :: "n"(N));
}

// ---------------------------------------------------------------------------
// fp16 GEMM (R14 version, passing at 499.8): block 128x256x32, 8 warps,
// warp 64x64, 4-stage cp.async, single barrier per k-tile.
// outH=1 -> fp16 output; outH=0 -> fp32 output.
// ---------------------------------------------------------------------------
__global__ __launch_bounds__(256, 1)
void gemm_h1(const __half* __restrict__ Ahg, size_t aBatch,
             const __half* __restrict__ Bg, size_t bBatch,
             void* __restrict__ Cvoid, size_t cBatch, int outH)
{
    extern __shared__ char smem[];
    const uint32_t sbase = smem_u32(smem);

    const int t    = threadIdx.x;
    const int lane = t & 31;
    const int wid  = t >> 5;
    const int b    = blockIdx.z;
    const int m0   = blockIdx.x * 128;
    const int n0   = blockIdx.y * 256;
    const int warpM = (wid >> 2) * 64;
    const int warpN = (wid & 3) * 64;

    const __half* Asrc = Ahg + (size_t)b * aBatch + (size_t)m0 * KTOT;
    const __half* Bsrc = Bg + (size_t)b * bBatch;

    const int g  = lane >> 3;
    const int lr = lane & 7;
    const uint32_t aLane = (uint32_t)(((g & 1) * 8 + lr) * LDA + (g >> 1) * 8) * 2;
    const uint32_t bLane = (uint32_t)(((g & 1) * 8 + lr) * LDB + (g >> 1) * 8) * 2;

    float acc[4][8][4];
#pragma unroll
    for (int i = 0; i < 4; i++)
#pragma unroll
        for (int j = 0; j < 8; j++)
#pragma unroll
            for (int e = 0; e < 4; e++) acc[i][j][e] = 0.f;

    auto load_stage = [&](int kt, int stg) {
        const uint32_t sb = sbase + stg * SST;
#pragma unroll
        for (int it = 0; it < 2; it++) {          // A: 512 x 16B
            int c = t + it * 256;
            int r = c >> 2, kc = c & 3;
            cpa16(sb + r * (LDA * 2) + kc * 16,
                  Asrc + (size_t)r * KTOT + kt * 32 + kc * 8);
        }
#pragma unroll
        for (int it = 0; it < 4; it++) {          // B: 1024 x 16B
            int c = t + it * 256;
            int r = c >> 5, nc = c & 31;
            cpa16(sb + B_OFF + r * (LDB * 2) + nc * 16,
                  Bsrc + (size_t)(kt * 32 + r) * HW + n0 + nc * 8);
        }
        cpa_commit();
    };

    const int KT = KTOT / 32;   // 12
    load_stage(0, 0);
    load_stage(1, 1);
    load_stage(2, 2);

    for (int kt = 0; kt < KT; kt++) {
        const int rem = KT - 1 - kt;
        if (rem >= 2)      cpa_wait<2>();
        else if (rem == 1) cpa_wait<1>();
        else               cpa_wait<0>();
        __syncthreads();
        if (kt + 3 < KT) load_stage(kt + 3, (kt + 3) % NSTG);

        const uint32_t sb = sbase + (kt % NSTG) * SST;
#pragma unroll
        for (int k16 = 0; k16 < 2; k16++) {
            uint32_t Ah[4][4];
#pragma unroll
            for (int i = 0; i < 4; i++)
                ldm_x4(Ah[i], sb + aLane
                              + (uint32_t)((warpM + i * 16) * LDA + k16 * 16) * 2);
            uint32_t Bf[8][2];
#pragma unroll
            for (int p = 0; p < 4; p++) {
                uint32_t r[4];
                uint32_t bo = sb + B_OFF + bLane
                            + (uint32_t)(k16 * 16 * LDB + warpN + p * 16) * 2;
                ldm_x4_t(r, bo);
                Bf[p * 2][0] = r[0]; Bf[p * 2][1] = r[1];
                Bf[p * 2 + 1][0] = r[2]; Bf[p * 2 + 1][1] = r[3];
            }
#pragma unroll
            for (int i = 0; i < 4; i++)
#pragma unroll
                for (int j = 0; j < 8; j++)
                    mma_h(acc[i][j], Ah[i], Bf[j][0], Bf[j][1]);
        }
    }

    const int erow = lane >> 2;
    const int ecol = (lane & 3) * 2;
    if (outH) {
        __half* Cp = (__half*)Cvoid + (size_t)b * cBatch;
#pragma unroll
        for (int i = 0; i < 4; i++)
#pragma unroll
            for (int j = 0; j < 8; j++) {
                __half* base = Cp + (size_t)(m0 + warpM + i * 16 + erow) * HW
                                  + n0 + warpN + j * 8 + ecol;
                __half2 v01 = __floats2half2_rn(acc[i][j][0], acc[i][j][1]);
                __half2 v23 = __floats2half2_rn(acc[i][j][2], acc[i][j][3]);
                *(__half2*)base = v01;
                *(__half2*)(base + 8 * HW) = v23;
            }
    } else {
        float* Cp = (float*)Cvoid + (size_t)b * cBatch;
#pragma unroll
        for (int i = 0; i < 4; i++)
#pragma unroll
            for (int j = 0; j < 8; j++) {
                float* base = Cp + (size_t)(m0 + warpM + i * 16 + erow) * HW
                                 + n0 + warpN + j * 8 + ecol;
                *(float2*)base = make_float2(acc[i][j][0], acc[i][j][1]);
                *(float2*)(base + 8 * HW) = make_float2(acc[i][j][2], acc[i][j][3]);
            }
    }
}

// ---------------------------------------------------------------------------
// Combined fp32 -> fp16 convert for X (first nx4 float4's) and W (next nw4).
// ---------------------------------------------------------------------------
__global__ __launch_bounds__(256)
void convprep(const float* __restrict__ x, __half* __restrict__ xh, int nx4,
              const float* __restrict__ w, __half* __restrict__ wh, int nw4)
{
    int i = blockIdx.x * 256 + threadIdx.x;
    const float* src;
    __half* dst;
    int j;
    if (i < nx4)            { src = x; dst = xh; j = i; }
    else if (i < nx4 + nw4) { src = w; dst = wh; j = i - nx4; }
    else return;
    float4 v = ((const float4*)src)[j];
    __half2 a = __floats2half2_rn(v.x, v.y);
    __half2 b = __floats2half2_rn(v.z, v.w);
    ((uint2*)dst)[j] = make_uint2(*(uint32_t*)&a, *(uint32_t*)&b);
}

// ---------------------------------------------------------------------------
// Depthwise 3x3 SAME conv on fp16 qkv, in place (R14 version, passing).
// ---------------------------------------------------------------------------
__global__ __launch_bounds__(256)
void dwconv3x3(__half* __restrict__ qkv, const float* __restrict__ wdw,
               float* __restrict__ inv)
{
    const int plane = blockIdx.x;
    const int b     = plane / C3;
    const int ch    = plane % C3;
    __half* p = qkv + (size_t)plane * HW;

    __shared__ __align__(16) __half s[66][88];
    const int t = threadIdx.x;

    {
        const int hr = (t >> 2) + 1;
        const int hc = (t & 1) ? 7 : 6;
        s[hr][hc + ((t & 2) ? 66 : 0)] = __ushort_as_half(0);
        if (t < 88) { s[0][t] = __ushort_as_half(0); s[65][t] = __ushort_as_half(0); }
    }
#pragma unroll
    for (int it = 0; it < 2; it++) {
        int i = t + it * 256;
        int y = i >> 3, x8 = (i & 7) * 8;
        *(uint4*)&s[y + 1][x8 + 8] = *(const uint4*)&p[y * 64 + x8];
    }

    float w[9];
#pragma unroll
    for (int j = 0; j < 9; j++) w[j] = wdw[ch * 9 + j];
    __syncthreads();

    const int y  = (t >> 3) * 2;
    const int x8 = (t & 7) * 8;

    float v[4][12];
#pragma unroll
    for (int r = 0; r < 4; r++) {
        __half2 hh[12];
        *(uint4*)&hh[0] = *(uint4*)&s[y + r][x8];
        *(uint4*)&hh[4] = *(uint4*)&s[y + r][x8 + 8];
        *(uint4*)&hh[8] = *(uint4*)&s[y + r][x8 + 16];
#pragma unroll
        for (int u = 0; u < 6; u++) {
            float2 f = __half22float2(hh[3 + u]);
            v[r][2 * u]     = f.x;
            v[r][2 * u + 1] = f.y;
        }
    }

    float o[2][8];
#pragma unroll
    for (int rr = 0; rr < 2; rr++)
#pragma unroll
        for (int j = 0; j < 8; j++) {
            float a = 0.f;
#pragma unroll
            for (int dy = 0; dy < 3; dy++)
#pragma unroll
                for (int dx = 0; dx < 3; dx++)
                    a = fmaf(v[rr + dy][j + 1 + dx], w[dy * 3 + dx], a);
            o[rr][j] = a;
        }

    float ss = 0.f;
#pragma unroll
    for (int rr = 0; rr < 2; rr++) {
        __half2 h0 = __floats2half2_rn(o[rr][0], o[rr][1]);
        __half2 h1 = __floats2half2_rn(o[rr][2], o[rr][3]);
        __half2 h2 = __floats2half2_rn(o[rr][4], o[rr][5]);
        __half2 h3 = __floats2half2_rn(o[rr][6], o[rr][7]);
        *(uint4*)&p[(y + rr) * 64 + x8] = make_uint4(
            *(uint32_t*)&h0, *(uint32_t*)&h1, *(uint32_t*)&h2, *(uint32_t*)&h3);
#pragma unroll
        for (int j = 0; j < 8; j++) ss = fmaf(o[rr][j], o[rr][j], ss);
    }

    if (ch < 2 * C_) {
        for (int off = 16; off > 0; off >>= 1)
            ss += __shfl_down_sync(0xffffffffu, ss, off);
        __shared__ float red[8];
        if ((t & 31) == 0) red[t >> 5] = ss;
        __syncthreads();
        if (t == 0) {
            float tot = 0.f;
#pragma unroll
            for (int i = 0; i < 8; i++) tot += red[i];
            inv[b * 2 * C_ + ch] = 1.f / fmaxf(sqrtf(tot), EPSN);
        }
    }
}

// ---------------------------------------------------------------------------
// Attention scores via mma.sync, DOUBLE-BUFFERED: two k64 tiles per barrier
// pair (halves barrier count, doubles outstanding loads and inter-barrier
// mma window). 96 threads; warp w owns the n16 column w of the 48x48 tile.
// ---------------------------------------------------------------------------
#define LDQ 72
#define QBUF (DH * LDQ)     // halves per buffer
__global__ __launch_bounds__(96)
void attn_scores(const __half* __restrict__ qkv)
{
    const int bh    = blockIdx.y;
    const int b     = bh >> 3;
    const int h     = bh & 7;
    const int chunk = blockIdx.x;
    const int t    = threadIdx.x;
    const int lane = t & 31;
    const int wid  = t >> 5;

    const __half* qbase = qkv + ((size_t)b * C3 + h * DH) * HW;
    const __half* kbase = qbase + (size_t)C_ * HW;

    __shared__ __align__(16) __half Qs[2][DH][LDQ];
    __shared__ __align__(16) __half Ks[2][DH][LDQ];
    const uint32_t qb = smem_u32(&Qs[0][0][0]);
    const uint32_t kb2 = smem_u32(&Ks[0][0][0]);

    const int g  = lane >> 3;
    const int lr = lane & 7;
    const uint32_t aLane = (uint32_t)(((g & 1) * 8 + lr) * LDQ + (g >> 1) * 8) * 2;
    const uint32_t bLane = (uint32_t)((wid * 16 + (g >> 1) * 8 + lr) * LDQ + (g & 1) * 8) * 2;

    float acc[3][2][4];
#pragma unroll
    for (int i = 0; i < 3; i++)
#pragma unroll
        for (int p = 0; p < 2; p++)
#pragma unroll
            for (int e = 0; e < 4; e++) acc[i][p][e] = 0.f;

    const int kb0 = chunk * CHUNK;
    for (int kt = 0; kt < CHUNK / 64; kt += 2) {    // 4 outer steps of 2x k64
        // load BOTH buffers before one barrier (16 iters of 96 threads)
#pragma unroll 4
        for (int i = t; i < DH * 16; i += 96) {
            const int buf = (i >= DH * 8);
            const int j   = i - buf * DH * 8;
            const int r   = j >> 3;
            const int c8  = (j & 7) * 8;
            const size_t goff = (size_t)r * HW + kb0 + (kt + buf) * 64 + c8;
            *(uint4*)&Qs[buf][r][c8] = *(const uint4*)&qbase[goff];
            *(uint4*)&Ks[buf][r][c8] = *(const uint4*)&kbase[goff];
        }
        __syncthreads();

#pragma unroll
        for (int buf = 0; buf < 2; buf++) {
            const uint32_t qoff = qb  + (uint32_t)buf * (QBUF * 2);
            const uint32_t koff = kb2 + (uint32_t)buf * (QBUF * 2);
#pragma unroll
            for (int k16 = 0; k16 < 4; k16++) {
                uint32_t Aq[3][4];
#pragma unroll
                for (int i = 0; i < 3; i++)
                    ldm_x4(Aq[i], qoff + aLane + (uint32_t)(i * 16 * LDQ + k16 * 16) * 2);
                uint32_t r[4];
                ldm_x4(r, koff + bLane + (uint32_t)(k16 * 16) * 2);
#pragma unroll
                for (int i = 0; i < 3; i++) {
                    mma_h(acc[i][0], Aq[i], r[0], r[1]);
                    mma_h(acc[i][1], Aq[i], r[2], r[3]);
                }
            }
        }
        __syncthreads();
    }

    const int erow = lane >> 2;
    const int ecol = (lane & 3) * 2;
    float* sp = &g_Spart[chunk][bh][0];
#pragma unroll
    for (int i = 0; i < 3; i++)
#pragma unroll
        for (int p = 0; p < 2; p++) {
            float* base = sp + (i * 16 + erow) * DH + wid * 16 + p * 8 + ecol;
            *(float2*)base = make_float2(acc[i][p][0], acc[i][p][1]);
            *(float2*)(base + 8 * DH) = make_float2(acc[i][p][2], acc[i][p][3]);
        }
}

// ---------------------------------------------------------------------------
// FUSED: reduce partials + norm scaling + temperature + softmax + W_eff.
// ---------------------------------------------------------------------------
__global__ __launch_bounds__(256)
void soft_weff(const float* __restrict__ temp, const float* __restrict__ inv,
               const float* __restrict__ wp, __half* __restrict__ eh)
{
    const int bh = blockIdx.x;
    const int b  = bh >> 3;
    const int h  = bh & 7;
    const int t  = threadIdx.x;

    __shared__ float As[DH][DH + 1];
    for (int i = t; i < DH * DH; i += 256) {
        float s = 0.f;
#pragma unroll
        for (int ch = 0; ch < NCH; ch++)
            s += g_Spart[ch][bh][i];
        As[i / DH][i % DH] = s;
    }
    __syncthreads();

    if (t < DH) {
        const float* ivq = inv + b * 2 * C_ + h * DH;
        const float* ivk = ivq + C_;
        const float rowscale = ivq[t] * temp[h];
        float vals[DH];
        float m = -INFINITY;
#pragma unroll
        for (int c = 0; c < DH; c++) {
            vals[c] = As[t][c] * rowscale * ivk[c];
            m = fmaxf(m, vals[c]);
        }
        float sum = 0.f;
#pragma unroll
        for (int c = 0; c < DH; c++) {
            vals[c] = expf(vals[c] - m);
            sum += vals[c];
        }
        float is = 1.f / sum;
#pragma unroll
        for (int c = 0; c < DH; c++) As[t][c] = vals[c] * is;
    }
    __syncthreads();

    for (int o = t; o < C_; o += 256) {
        float wrow[DH];
#pragma unroll
        for (int d = 0; d < DH; d++) wrow[d] = wp[(size_t)o * C_ + h * DH + d];
#pragma unroll 4
        for (int e = 0; e < DH; e++) {
            float acc = 0.f;
#pragma unroll
            for (int d = 0; d < DH; d++) acc = fmaf(wrow[d], As[d][e], acc);
            eh[((size_t)b * C_ + o) * C_ + h * DH + e] = __float2half(acc);
        }
    }
}

// ---------------------------------------------------------------------------
extern "C" void kernel_launch(void* const* d_in, const int* in_sizes, int n_in,
                              void* d_out, int out_size)
{
    const float* x      = (const float*)d_in[0];
    const float* w_qkv  = (const float*)d_in[1];
    const float* w_dw   = (const float*)d_in[2];
    const float* w_proj = (const float*)d_in[3];
    const float* temp   = (const float*)d_in[4];
    float* out = (float*)d_out;

    float* inv;
    __half *qkv16, *W0, *T0, *We0;
    cudaGetSymbolAddress((void**)&qkv16, g_qkv16);
    cudaGetSymbolAddress((void**)&inv, g_inv);
    cudaGetSymbolAddress((void**)&W0, g_W0);
    cudaGetSymbolAddress((void**)&T0, g_T0);
    cudaGetSymbolAddress((void**)&We0, g_We0);

    cudaFuncSetAttribute(gemm_h1, cudaFuncAttributeMaxDynamicSharedMemorySize, GSMEM);

    const int nx4 = B_ * C_ * HW / 4;
    const int nw4 = C3 * C_ / 4;
    // 1) X,W -> fp16 (one launch)
    convprep<<<(nx4 + nw4 + 255) / 256, 256>>>(x, T0, nx4, w_qkv, W0, nw4);
    // 2) qkv16 = W_qkv @ X  (fp16 output)
    gemm_h1<<<dim3(C3 / 128, HW / 256, B_), 256, GSMEM>>>(
        W0, 0, T0, (size_t)C_ * HW, qkv16, (size_t)C3 * HW, 1);
    // 3) dwconv in place on fp16 qkv + fused q/k norms
    dwconv3x3<<<B_ * C3, 256>>>(qkv16, w_dw, inv);
    // 4) attention scores via mma (double-buffered)
    attn_scores<<<dim3(NCH, B_ * NH), 96>>>(qkv16);
    // 5) fused softmax + W_eff
    soft_weff<<<B_ * NH, 256>>>(temp, inv, w_proj, We0);
    // 6) out = W_eff[b] @ V  (fp32 output)
    gemm_h1<<<dim3(C_ / 128, HW / 256, B_), 256, GSMEM>>>(
        We0, (size_t)C_ * C_, qkv16 + (size_t)2 * C_ * HW, (size_t)C3 * HW,
        out, (size_t)C_ * HW, 0);
}

// round 17
// speedup vs baseline: 1.1376x; 1.0705x over previous
#include <cuda_runtime.h>
#include <cuda.h>
#include <cuda_fp16.h>
#include <math.h>
#include <stdint.h>

// Problem constants (fixed shapes)
#define B_   16
#define C_   384
#define C3   1152
#define HW   4096
#define NH   8
#define DH   48
#define NCH  8
#define CHUNK 512
#define EPSN 1e-12f
#define KTOT 384

// GEMM smem geometry: block 128(M) x 256(N) x 64(K), 4-stage cp.async
#define KTILE 64
#define LDA 72
#define LDB 264
#define A_SZ   (128 * LDA * 2)            // 18432
#define B_SZ   (KTILE * LDB * 2)          // 33792
#define B_OFF  A_SZ
#define SST    (B_OFF + B_SZ)             // 52224
#define NSTG   4
#define GSMEM  (NSTG * SST)               // 208896

// ---------------- scratch (__device__ globals; no runtime alloc) -----------
__device__ __align__(128) __half g_qkv16[(size_t)B_ * C3 * HW];     // 151 MB
__device__ float g_inv[B_ * 2 * C_];
__device__ float g_Spart[NCH][B_ * NH][DH * DH];
__device__ __align__(128) __half g_W0[C3 * C_];                     // Wh [m][k]
__device__ __align__(128) __half g_T0[(size_t)B_ * C_ * HW];        // X fp16 [k][n]
__device__ __align__(128) __half g_We0[B_ * C_ * C_];               // Weh [m][k]

// ---------------- PTX helpers ----------------------------------------------
__device__ __forceinline__ uint32_t smem_u32(const void* p) {
    uint32_t a;
    asm("{ .reg .u64 t; cvta.to.shared.u64 t, %1; cvt.u32.u64 %0, t; }"
        : "=r"(a) : "l"(p));
    return a;
}
__device__ __forceinline__ void ldm_x4(uint32_t* r, uint32_t addr) {
    asm volatile("ldmatrix.sync.aligned.m8n8.x4.shared.b16 {%0,%1,%2,%3}, [%4];"
        : "=r"(r[0]), "=r"(r[1]), "=r"(r[2]), "=r"(r[3]) : "r"(addr));
}
__device__ __forceinline__ void ldm_x4_t(uint32_t* r, uint32_t addr) {
    asm volatile("ldmatrix.sync.aligned.m8n8.x4.trans.shared.b16 {%0,%1,%2,%3}, [%4];"
        : "=r"(r[0]), "=r"(r[1]), "=r"(r[2]), "=r"(r[3]) : "r"(addr));
}
__device__ __forceinline__ void mma_h(float* c, const uint32_t* a,
                                      uint32_t b0, uint32_t b1) {
    asm volatile(
        "mma.sync.aligned.m16n8k16.row.col.f32.f16.f16.f32 "
        "{%0,%1,%2,%3}, {%4,%5,%6,%7}, {%8,%9}, {%0,%1,%2,%3};"
        : "+f"(c[0]), "+f"(c[1]), "+f"(c[2]), "+f"(c[3])
        : "r"(a[0]), "r"(a[1]), "r"(a[2]), "r"(a[3]), "r"(b0), "r"(b1));
}
__device__ __forceinline__ void cpa16(uint32_t s, const void* g) {
    asm volatile("cp.async.cg.shared.global [%0], [%1], 16;" :: "r"(s), "l"(g));
}
__device__ __forceinline__ void cpa_commit() {
    asm volatile("cp.async.commit_group;");
}
template <int N> __device__ __forceinline__ void cpa_wait() {
    asm volatile("cp.async.wait_group %0;" :: "n"(N));
}

// ---------------------------------------------------------------------------
// fp16 GEMM: block 128x256x64, 8 warps, warp 64x64, 4-stage cp.async,
// single barrier per k-tile (6 tiles for K=384).
// outH=1 -> fp16 output; outH=0 -> fp32 output.
// ---------------------------------------------------------------------------
__global__ __launch_bounds__(256, 1)
void gemm_h1(const __half* __restrict__ Ahg, size_t aBatch,
             const __half* __restrict__ Bg, size_t bBatch,
             void* __restrict__ Cvoid, size_t cBatch, int outH)
{
    extern __shared__ char smem[];
    const uint32_t sbase = smem_u32(smem);

    const int t    = threadIdx.x;
    const int lane = t & 31;
    const int wid  = t >> 5;
    const int b    = blockIdx.z;
    const int m0   = blockIdx.x * 128;
    const int n0   = blockIdx.y * 256;
    const int warpM = (wid >> 2) * 64;
    const int warpN = (wid & 3) * 64;

    const __half* Asrc = Ahg + (size_t)b * aBatch + (size_t)m0 * KTOT;
    const __half* Bsrc = Bg + (size_t)b * bBatch;

    const int g  = lane >> 3;
    const int lr = lane & 7;
    const uint32_t aLane = (uint32_t)(((g & 1) * 8 + lr) * LDA + (g >> 1) * 8) * 2;
    const uint32_t bLane = (uint32_t)(((g & 1) * 8 + lr) * LDB + (g >> 1) * 8) * 2;

    float acc[4][8][4];
#pragma unroll
    for (int i = 0; i < 4; i++)
#pragma unroll
        for (int j = 0; j < 8; j++)
#pragma unroll
            for (int e = 0; e < 4; e++) acc[i][j][e] = 0.f;

    auto load_stage = [&](int kt, int stg) {
        const uint32_t sb = sbase + stg * SST;
#pragma unroll
        for (int it = 0; it < 4; it++) {          // A: 1024 x 16B (128x64)
            int c = t + it * 256;
            int r = c >> 3, kc = c & 7;
            cpa16(sb + r * (LDA * 2) + kc * 16,
                  Asrc + (size_t)r * KTOT + kt * KTILE + kc * 8);
        }
#pragma unroll
        for (int it = 0; it < 8; it++) {          // B: 2048 x 16B (64x256)
            int c = t + it * 256;
            int r = c >> 5, nc = c & 31;
            cpa16(sb + B_OFF + r * (LDB * 2) + nc * 16,
                  Bsrc + (size_t)(kt * KTILE + r) * HW + n0 + nc * 8);
        }
        cpa_commit();
    };

    const int KT = KTOT / KTILE;   // 6
    load_stage(0, 0);
    load_stage(1, 1);
    load_stage(2, 2);

    for (int kt = 0; kt < KT; kt++) {
        const int rem = KT - 1 - kt;
        if (rem >= 2)      cpa_wait<2>();
        else if (rem == 1) cpa_wait<1>();
        else               cpa_wait<0>();
        __syncthreads();
        // safe: barrier guarantees all warps finished stage (kt-1)%4 ==
        // (kt+3)%4 during iteration kt-1.
        if (kt + 3 < KT) load_stage(kt + 3, (kt + 3) % NSTG);

        const uint32_t sb = sbase + (kt % NSTG) * SST;
#pragma unroll
        for (int k16 = 0; k16 < 4; k16++) {
            uint32_t Ah[4][4];
#pragma unroll
            for (int i = 0; i < 4; i++)
                ldm_x4(Ah[i], sb + aLane
                              + (uint32_t)((warpM + i * 16) * LDA + k16 * 16) * 2);
            uint32_t Bf[8][2];
#pragma unroll
            for (int p = 0; p < 4; p++) {
                uint32_t r[4];
                uint32_t bo = sb + B_OFF + bLane
                            + (uint32_t)(k16 * 16 * LDB + warpN + p * 16) * 2;
                ldm_x4_t(r, bo);
                Bf[p * 2][0] = r[0]; Bf[p * 2][1] = r[1];
                Bf[p * 2 + 1][0] = r[2]; Bf[p * 2 + 1][1] = r[3];
            }
#pragma unroll
            for (int i = 0; i < 4; i++)
#pragma unroll
                for (int j = 0; j < 8; j++)
                    mma_h(acc[i][j], Ah[i], Bf[j][0], Bf[j][1]);
        }
    }

    const int erow = lane >> 2;
    const int ecol = (lane & 3) * 2;
    if (outH) {
        __half* Cp = (__half*)Cvoid + (size_t)b * cBatch;
#pragma unroll
        for (int i = 0; i < 4; i++)
#pragma unroll
            for (int j = 0; j < 8; j++) {
                __half* base = Cp + (size_t)(m0 + warpM + i * 16 + erow) * HW
                                  + n0 + warpN + j * 8 + ecol;
                __half2 v01 = __floats2half2_rn(acc[i][j][0], acc[i][j][1]);
                __half2 v23 = __floats2half2_rn(acc[i][j][2], acc[i][j][3]);
                *(__half2*)base = v01;
                *(__half2*)(base + 8 * HW) = v23;
            }
    } else {
        float* Cp = (float*)Cvoid + (size_t)b * cBatch;
#pragma unroll
        for (int i = 0; i < 4; i++)
#pragma unroll
            for (int j = 0; j < 8; j++) {
                float* base = Cp + (size_t)(m0 + warpM + i * 16 + erow) * HW
                                 + n0 + warpN + j * 8 + ecol;
                *(float2*)base = make_float2(acc[i][j][0], acc[i][j][1]);
                *(float2*)(base + 8 * HW) = make_float2(acc[i][j][2], acc[i][j][3]);
            }
    }
}

// ---------------------------------------------------------------------------
// Combined fp32 -> fp16 convert for X (first nx4 float4's) and W (next nw4).
// ---------------------------------------------------------------------------
__global__ __launch_bounds__(256)
void convprep(const float* __restrict__ x, __half* __restrict__ xh, int nx4,
              const float* __restrict__ w, __half* __restrict__ wh, int nw4)
{
    int i = blockIdx.x * 256 + threadIdx.x;
    const float* src;
    __half* dst;
    int j;
    if (i < nx4)            { src = x; dst = xh; j = i; }
    else if (i < nx4 + nw4) { src = w; dst = wh; j = i - nx4; }
    else return;
    float4 v = ((const float4*)src)[j];
    __half2 a = __floats2half2_rn(v.x, v.y);
    __half2 b = __floats2half2_rn(v.z, v.w);
    ((uint2*)dst)[j] = make_uint2(*(uint32_t*)&a, *(uint32_t*)&b);
}

// ---------------------------------------------------------------------------
// Depthwise 3x3 SAME conv on fp16 qkv, in place (R14/R16 version, passing).
// ---------------------------------------------------------------------------
__global__ __launch_bounds__(256)
void dwconv3x3(__half* __restrict__ qkv, const float* __restrict__ wdw,
               float* __restrict__ inv)
{
    const int plane = blockIdx.x;
    const int b     = plane / C3;
    const int ch    = plane % C3;
    __half* p = qkv + (size_t)plane * HW;

    __shared__ __align__(16) __half s[66][88];
    const int t = threadIdx.x;

    {
        const int hr = (t >> 2) + 1;
        const int hc = (t & 1) ? 7 : 6;
        s[hr][hc + ((t & 2) ? 66 : 0)] = __ushort_as_half(0);
        if (t < 88) { s[0][t] = __ushort_as_half(0); s[65][t] = __ushort_as_half(0); }
    }
#pragma unroll
    for (int it = 0; it < 2; it++) {
        int i = t + it * 256;
        int y = i >> 3, x8 = (i & 7) * 8;
        *(uint4*)&s[y + 1][x8 + 8] = *(const uint4*)&p[y * 64 + x8];
    }

    float w[9];
#pragma unroll
    for (int j = 0; j < 9; j++) w[j] = wdw[ch * 9 + j];
    __syncthreads();

    const int y  = (t >> 3) * 2;
    const int x8 = (t & 7) * 8;

    float v[4][12];
#pragma unroll
    for (int r = 0; r < 4; r++) {
        __half2 hh[12];
        *(uint4*)&hh[0] = *(uint4*)&s[y + r][x8];
        *(uint4*)&hh[4] = *(uint4*)&s[y + r][x8 + 8];
        *(uint4*)&hh[8] = *(uint4*)&s[y + r][x8 + 16];
#pragma unroll
        for (int u = 0; u < 6; u++) {
            float2 f = __half22float2(hh[3 + u]);
            v[r][2 * u]     = f.x;
            v[r][2 * u + 1] = f.y;
        }
    }

    float o[2][8];
#pragma unroll
    for (int rr = 0; rr < 2; rr++)
#pragma unroll
        for (int j = 0; j < 8; j++) {
            float a = 0.f;
#pragma unroll
            for (int dy = 0; dy < 3; dy++)
#pragma unroll
                for (int dx = 0; dx < 3; dx++)
                    a = fmaf(v[rr + dy][j + 1 + dx], w[dy * 3 + dx], a);
            o[rr][j] = a;
        }

    float ss = 0.f;
#pragma unroll
    for (int rr = 0; rr < 2; rr++) {
        __half2 h0 = __floats2half2_rn(o[rr][0], o[rr][1]);
        __half2 h1 = __floats2half2_rn(o[rr][2], o[rr][3]);
        __half2 h2 = __floats2half2_rn(o[rr][4], o[rr][5]);
        __half2 h3 = __floats2half2_rn(o[rr][6], o[rr][7]);
        *(uint4*)&p[(y + rr) * 64 + x8] = make_uint4(
            *(uint32_t*)&h0, *(uint32_t*)&h1, *(uint32_t*)&h2, *(uint32_t*)&h3);
#pragma unroll
        for (int j = 0; j < 8; j++) ss = fmaf(o[rr][j], o[rr][j], ss);
    }

    if (ch < 2 * C_) {
        for (int off = 16; off > 0; off >>= 1)
            ss += __shfl_down_sync(0xffffffffu, ss, off);
        __shared__ float red[8];
        if ((t & 31) == 0) red[t >> 5] = ss;
        __syncthreads();
        if (t == 0) {
            float tot = 0.f;
#pragma unroll
            for (int i = 0; i < 8; i++) tot += red[i];
            inv[b * 2 * C_ + ch] = 1.f / fmaxf(sqrtf(tot), EPSN);
        }
    }
}

// ---------------------------------------------------------------------------
// Attention scores via mma.sync, double-buffered (R16 version, passing).
// ---------------------------------------------------------------------------
#define LDQ 72
#define QBUF (DH * LDQ)
__global__ __launch_bounds__(96)
void attn_scores(const __half* __restrict__ qkv)
{
    const int bh    = blockIdx.y;
    const int b     = bh >> 3;
    const int h     = bh & 7;
    const int chunk = blockIdx.x;
    const int t    = threadIdx.x;
    const int lane = t & 31;
    const int wid  = t >> 5;

    const __half* qbase = qkv + ((size_t)b * C3 + h * DH) * HW;
    const __half* kbase = qbase + (size_t)C_ * HW;

    __shared__ __align__(16) __half Qs[2][DH][LDQ];
    __shared__ __align__(16) __half Ks[2][DH][LDQ];
    const uint32_t qb = smem_u32(&Qs[0][0][0]);
    const uint32_t kb2 = smem_u32(&Ks[0][0][0]);

    const int g  = lane >> 3;
    const int lr = lane & 7;
    const uint32_t aLane = (uint32_t)(((g & 1) * 8 + lr) * LDQ + (g >> 1) * 8) * 2;
    const uint32_t bLane = (uint32_t)((wid * 16 + (g >> 1) * 8 + lr) * LDQ + (g & 1) * 8) * 2;

    float acc[3][2][4];
#pragma unroll
    for (int i = 0; i < 3; i++)
#pragma unroll
        for (int p = 0; p < 2; p++)
#pragma unroll
            for (int e = 0; e < 4; e++) acc[i][p][e] = 0.f;

    const int kb0 = chunk * CHUNK;
    for (int kt = 0; kt < CHUNK / 64; kt += 2) {
#pragma unroll 4
        for (int i = t; i < DH * 16; i += 96) {
            const int buf = (i >= DH * 8);
            const int j   = i - buf * DH * 8;
            const int r   = j >> 3;
            const int c8  = (j & 7) * 8;
            const size_t goff = (size_t)r * HW + kb0 + (kt + buf) * 64 + c8;
            *(uint4*)&Qs[buf][r][c8] = *(const uint4*)&qbase[goff];
            *(uint4*)&Ks[buf][r][c8] = *(const uint4*)&kbase[goff];
        }
        __syncthreads();

#pragma unroll
        for (int buf = 0; buf < 2; buf++) {
            const uint32_t qoff = qb  + (uint32_t)buf * (QBUF * 2);
            const uint32_t koff = kb2 + (uint32_t)buf * (QBUF * 2);
#pragma unroll
            for (int k16 = 0; k16 < 4; k16++) {
                uint32_t Aq[3][4];
#pragma unroll
                for (int i = 0; i < 3; i++)
                    ldm_x4(Aq[i], qoff + aLane + (uint32_t)(i * 16 * LDQ + k16 * 16) * 2);
                uint32_t r[4];
                ldm_x4(r, koff + bLane + (uint32_t)(k16 * 16) * 2);
#pragma unroll
                for (int i = 0; i < 3; i++) {
                    mma_h(acc[i][0], Aq[i], r[0], r[1]);
                    mma_h(acc[i][1], Aq[i], r[2], r[3]);
                }
            }
        }
        __syncthreads();
    }

    const int erow = lane >> 2;
    const int ecol = (lane & 3) * 2;
    float* sp = &g_Spart[chunk][bh][0];
#pragma unroll
    for (int i = 0; i < 3; i++)
#pragma unroll
        for (int p = 0; p < 2; p++) {
            float* base = sp + (i * 16 + erow) * DH + wid * 16 + p * 8 + ecol;
            *(float2*)base = make_float2(acc[i][p][0], acc[i][p][1]);
            *(float2*)(base + 8 * DH) = make_float2(acc[i][p][2], acc[i][p][3]);
        }
}

// ---------------------------------------------------------------------------
// FUSED: reduce partials + norm scaling + temperature + softmax + W_eff.
// ---------------------------------------------------------------------------
__global__ __launch_bounds__(256)
void soft_weff(const float* __restrict__ temp, const float* __restrict__ inv,
               const float* __restrict__ wp, __half* __restrict__ eh)
{
    const int bh = blockIdx.x;
    const int b  = bh >> 3;
    const int h  = bh & 7;
    const int t  = threadIdx.x;

    __shared__ float As[DH][DH + 1];
    for (int i = t; i < DH * DH; i += 256) {
        float s = 0.f;
#pragma unroll
        for (int ch = 0; ch < NCH; ch++)
            s += g_Spart[ch][bh][i];
        As[i / DH][i % DH] = s;
    }
    __syncthreads();

    if (t < DH) {
        const float* ivq = inv + b * 2 * C_ + h * DH;
        const float* ivk = ivq + C_;
        const float rowscale = ivq[t] * temp[h];
        float vals[DH];
        float m = -INFINITY;
#pragma unroll
        for (int c = 0; c < DH; c++) {
            vals[c] = As[t][c] * rowscale * ivk[c];
            m = fmaxf(m, vals[c]);
        }
        float sum = 0.f;
#pragma unroll
        for (int c = 0; c < DH; c++) {
            vals[c] = expf(vals[c] - m);
            sum += vals[c];
        }
        float is = 1.f / sum;
#pragma unroll
        for (int c = 0; c < DH; c++) As[t][c] = vals[c] * is;
    }
    __syncthreads();

    for (int o = t; o < C_; o += 256) {
        float wrow[DH];
#pragma unroll
        for (int d = 0; d < DH; d++) wrow[d] = wp[(size_t)o * C_ + h * DH + d];
#pragma unroll 4
        for (int e = 0; e < DH; e++) {
            float acc = 0.f;
#pragma unroll
            for (int d = 0; d < DH; d++) acc = fmaf(wrow[d], As[d][e], acc);
            eh[((size_t)b * C_ + o) * C_ + h * DH + e] = __float2half(acc);
        }
    }
}

// ---------------------------------------------------------------------------
extern "C" void kernel_launch(void* const* d_in, const int* in_sizes, int n_in,
                              void* d_out, int out_size)
{
    const float* x      = (const float*)d_in[0];
    const float* w_qkv  = (const float*)d_in[1];
    const float* w_dw   = (const float*)d_in[2];
    const float* w_proj = (const float*)d_in[3];
    const float* temp   = (const float*)d_in[4];
    float* out = (float*)d_out;

    float* inv;
    __half *qkv16, *W0, *T0, *We0;
    cudaGetSymbolAddress((void**)&qkv16, g_qkv16);
    cudaGetSymbolAddress((void**)&inv, g_inv);
    cudaGetSymbolAddress((void**)&W0, g_W0);
    cudaGetSymbolAddress((void**)&T0, g_T0);
    cudaGetSymbolAddress((void**)&We0, g_We0);

    cudaFuncSetAttribute(gemm_h1, cudaFuncAttributeMaxDynamicSharedMemorySize, GSMEM);

    const int nx4 = B_ * C_ * HW / 4;
    const int nw4 = C3 * C_ / 4;
    // 1) X,W -> fp16 (one launch)
    convprep<<<(nx4 + nw4 + 255) / 256, 256>>>(x, T0, nx4, w_qkv, W0, nw4);
    // 2) qkv16 = W_qkv @ X  (fp16 output)
    gemm_h1<<<dim3(C3 / 128, HW / 256, B_), 256, GSMEM>>>(
        W0, 0, T0, (size_t)C_ * HW, qkv16, (size_t)C3 * HW, 1);
    // 3) dwconv in place on fp16 qkv + fused q/k norms
    dwconv3x3<<<B_ * C3, 256>>>(qkv16, w_dw, inv);
    // 4) attention scores via mma (double-buffered)
    attn_scores<<<dim3(NCH, B_ * NH), 96>>>(qkv16);
    // 5) fused softmax + W_eff
    soft_weff<<<B_ * NH, 256>>>(temp, inv, w_proj, We0);
    // 6) out = W_eff[b] @ V  (fp32 output)
    gemm_h1<<<dim3(C_ / 128, HW / 256, B_), 256, GSMEM>>>(
        We0, (size_t)C_ * C_, qkv16 + (size_t)2 * C_ * HW, (size_t)C3 * HW,
        out, (size_t)C_ * HW, 0);
}